// round 16
// baseline (speedup 1.0000x reference)
#include <cuda_runtime.h>
#include <cuda_fp16.h>
#include <cstdint>

// ---------------------------------------------------------------------------
// GCN layer:  out = D^-1/2 (adj+I) D^-1/2 @ ((x@W1^T+b1)@W2^T + b2)
// Folded:  r = rsqrt(rowsum(adj)+1); h1 = x@W1^T+b1;
//          g = r ⊙ (h1@W2^T+b2);     out = diag(r) * (adj@g + g)
// Chain (3 kernels):
//   fused_pre : [0,128) gemm1 tf32 -> Ahp, [128,640) rowsum + adj pack
//               (R16: cp.async double-buffered input stream),
//               [640,656) W2 pack
//   gemm2     : fp16 m16n8k16 (KT=4); writes g fp16 + Bp fragments
//   gemm3     : fp16 m16n8k16, CTA 128x256, warp 64x64, 4 stages,
//               2 ktiles per barrier round, split issue placement
// ---------------------------------------------------------------------------

#define NN   8192
#define HID  256
#define OUTF 512

__device__ __half g_g16[NN * OUTF];      // 8 MB  g (fp16, row-major)
__device__ uint4 g_Bp[512 * 512 * 2];    // 8 MB  g fragment-packed fp16 (gemm3 B)
__device__ uint2 g_Ap[512 * 128 * 256];  // 128 MB adj A-fragments fp16
__device__ uint2 g_Ahp[512 * 4 * 256];   // 4 MB  h1 A-fragments fp16 (gemm2 A)
__device__ uint2 g_Bp2[16 * 512 * 4];    // 256 KB W2 B-fragments fp16 (gemm2 B)
__device__ float g_r[NN];

__device__ __forceinline__ uint32_t f2tf(float f) {
    uint32_t u;
    asm("cvt.rna.tf32.f32 %0, %1;" : "=r"(u) : "f"(f));
    return u;
}
// pack {lo, hi} floats into f16x2 (lo in bits[15:0])
__device__ __forceinline__ uint32_t pk16(float hi, float lo) {
    uint32_t u;
    asm("cvt.rn.f16x2.f32 %0, %1, %2;" : "=r"(u) : "f"(hi), "f"(lo));
    return u;
}
__device__ __forceinline__ uint32_t smem_u32(const void* p) {
    uint32_t a;
    asm("{ .reg .u64 t; cvta.to.shared.u64 t, %1; cvt.u32.u64 %0, t; }"
        : "=r"(a) : "l"(p));
    return a;
}
__device__ __forceinline__ void mma_tf32(float* c, const uint32_t* a,
                                         uint32_t b0, uint32_t b1) {
    asm volatile(
        "mma.sync.aligned.m16n8k8.row.col.f32.tf32.tf32.f32 "
        "{%0,%1,%2,%3},{%4,%5,%6,%7},{%8,%9},{%0,%1,%2,%3};"
        : "+f"(c[0]), "+f"(c[1]), "+f"(c[2]), "+f"(c[3])
        : "r"(a[0]), "r"(a[1]), "r"(a[2]), "r"(a[3]), "r"(b0), "r"(b1));
}
__device__ __forceinline__ void mma_fp16(float* c, const uint32_t* a,
                                         const uint32_t* b) {
    asm volatile(
        "mma.sync.aligned.m16n8k16.row.col.f32.f16.f16.f32 "
        "{%0,%1,%2,%3},{%4,%5,%6,%7},{%8,%9},{%0,%1,%2,%3};"
        : "+f"(c[0]), "+f"(c[1]), "+f"(c[2]), "+f"(c[3])
        : "r"(a[0]), "r"(a[1]), "r"(a[2]), "r"(a[3]), "r"(b[0]), "r"(b[1]));
}

#define CP_ASYNC16(dst, src) \
    asm volatile("cp.async.cg.shared.global [%0], [%1], 16;" \
                 :: "r"(dst), "l"(src) : "memory")
#define CP_COMMIT() asm volatile("cp.async.commit_group;" ::: "memory")
#define CP_WAIT0()  asm volatile("cp.async.wait_group 0;" ::: "memory")
#define CP_WAIT1()  asm volatile("cp.async.wait_group 1;" ::: "memory")
#define CP_WAIT2()  asm volatile("cp.async.wait_group 2;" ::: "memory")

// ---------------------------------------------------------------------------
// fused_pre (656 blocks, 256 threads):
//   [0,128)   gemm1: h1 = x@W1^T + b1 -> fp16 A-fragment units into Ahp
//   [128,640) rowsum r + adj -> fp16 A-fragment units into Ap
//             (cp.async double-buffered: 2 x 16 KB inbuf + 9 KB stage)
//   [640,656) W2 -> fp16 B-fragment units into Bp2
// ---------------------------------------------------------------------------
#define RS_INBUF  16384                       // one round: 16 rows x 256 cols fp32
#define RS_SMEM   (2 * RS_INBUF + 4 * 288 * 8)  // 41984
#define G1_SMEM   (2 * 128 * 36 * 4)          // 36864
#define PRE_SMEM  (RS_SMEM > G1_SMEM ? RS_SMEM : G1_SMEM)

__global__ __launch_bounds__(256) void fused_pre(
    const float* __restrict__ adj, float* __restrict__ r, uint2* __restrict__ Ap,
    const float* __restrict__ x, const float* __restrict__ W1,
    uint2* __restrict__ Ahp, const float* __restrict__ b1,
    const float* __restrict__ W2, uint2* __restrict__ Bp2) {

    extern __shared__ __align__(16) char dyn[];
    const int tid = threadIdx.x;

    if (blockIdx.x < 128) {
        // ---------------- gemm1 (tf32), epilogue -> Ahp fragments ----------
        const int K_ = 512;
        float* As = reinterpret_cast<float*>(dyn);
        float* Bs = As + 128 * 36;

        const int lane = tid & 31;
        const int warp = tid >> 5;
        const int wm = warp >> 1;
        const int wn = warp & 1;
        const int bx = blockIdx.x;
        const int m0 = (bx >> 1) * 128;
        const int n0 = (bx & 1) * 128;
        const int KT = K_ / 32;

        float acc[2][8][4];
#pragma unroll
        for (int mi = 0; mi < 2; mi++)
#pragma unroll
            for (int nj = 0; nj < 8; nj++)
#pragma unroll
                for (int q = 0; q < 4; q++) acc[mi][nj][q] = 0.f;

        float4 pa[4], pb[4];

        auto loadA = [&](int kt, float4* p) {
#pragma unroll
            for (int i = 0; i < 4; i++) {
                int idx = tid + i * 256;
                int row = idx >> 3;
                int kc  = (idx & 7) << 2;
                p[i] = *reinterpret_cast<const float4*>(
                    &x[(size_t)(m0 + row) * K_ + kt * 32 + kc]);
            }
        };
        auto storeA = [&](const float4* p) {
#pragma unroll
            for (int i = 0; i < 4; i++) {
                int idx = tid + i * 256;
                int row = idx >> 3;
                int kc  = (idx & 7) << 2;
                uint4 t = make_uint4(f2tf(p[i].x), f2tf(p[i].y),
                                     f2tf(p[i].z), f2tf(p[i].w));
                *reinterpret_cast<uint4*>(&As[row * 36 + kc]) = t;
            }
        };
        auto loadB = [&](int kt, float4* p) {
#pragma unroll
            for (int i = 0; i < 4; i++) {
                int idx = tid + i * 256;
                int row = idx >> 3;
                int kc  = (idx & 7) << 2;
                p[i] = *reinterpret_cast<const float4*>(
                    &W1[(size_t)(n0 + row) * K_ + kt * 32 + kc]);
            }
        };
        auto storeB = [&](const float4* p) {
#pragma unroll
            for (int i = 0; i < 4; i++) {
                int idx = tid + i * 256;
                int row = idx >> 3;
                int kc  = (idx & 7) << 2;
                uint4 t = make_uint4(f2tf(p[i].x), f2tf(p[i].y),
                                     f2tf(p[i].z), f2tf(p[i].w));
                *reinterpret_cast<uint4*>(&Bs[row * 36 + kc]) = t;
            }
        };

        loadA(0, pa); loadB(0, pb);
        storeA(pa);   storeB(pb);
        __syncthreads();

        for (int kt = 0; kt < KT; kt++) {
            if (kt + 1 < KT) { loadA(kt + 1, pa); loadB(kt + 1, pb); }
#pragma unroll
            for (int kk = 0; kk < 4; kk++) {
                uint32_t afr[2][4];
#pragma unroll
                for (int mi = 0; mi < 2; mi++) {
                    int r0 = wm * 32 + mi * 16 + (lane >> 2);
                    int kb = kk * 8 + (lane & 3);
                    afr[mi][0] = __float_as_uint(As[r0 * 36 + kb]);
                    afr[mi][1] = __float_as_uint(As[(r0 + 8) * 36 + kb]);
                    afr[mi][2] = __float_as_uint(As[r0 * 36 + kb + 4]);
                    afr[mi][3] = __float_as_uint(As[(r0 + 8) * 36 + kb + 4]);
                }
#pragma unroll
                for (int nj = 0; nj < 8; nj++) {
                    int nn = wn * 64 + nj * 8 + (lane >> 2);
                    int k0 = kk * 8 + (lane & 3);
                    uint32_t b0 = __float_as_uint(Bs[nn * 36 + k0]);
                    uint32_t b1_ = __float_as_uint(Bs[nn * 36 + k0 + 4]);
                    mma_tf32(acc[0][nj], afr[0], b0, b1_);
                    mma_tf32(acc[1][nj], afr[1], b0, b1_);
                }
            }
            __syncthreads();
            if (kt + 1 < KT) {
                storeA(pa); storeB(pb);
                __syncthreads();
            }
        }

        // epilogue: scatter fragments into smem, then coalesced uint4 stores.
        uint2* stg = reinterpret_cast<uint2*>(dyn);   // 16 regions x 256 units
        const int lr  = lane >> 2;
        const int lc2 = (lane & 3) * 2;
#pragma unroll
        for (int mi = 0; mi < 2; mi++) {
#pragma unroll
            for (int nj = 0; nj < 8; nj++) {
                int rowl = wm * 32 + mi * 16 + lr;     // local row 0..127
                int coll = wn * 64 + nj * 8 + lc2;     // local col 0..127
                int col  = n0 + coll;
                const float* cc = acc[mi][nj];
                uint2 u;
                u.x = pk16(cc[1] + b1[col + 1], cc[0] + b1[col]);  // row
                u.y = pk16(cc[3] + b1[col + 1], cc[2] + b1[col]);  // row+8
                int lb  = rowl >> 4;                   // 0..7
                int lk  = coll >> 6;                   // 0..1
                int kpl = (coll & 63) >> 1;
                int gx  = lr ^ ((kpl & 3) << 1);
                stg[(lb * 2 + lk) * 256 + kpl * 8 + gx] = u;
            }
        }
        __syncthreads();
        const int kt2base = n0 >> 6;
        const uint4* s4 = reinterpret_cast<const uint4*>(dyn);
#pragma unroll
        for (int i = 0; i < 8; i++) {
            int task = tid + i * 256;                  // 0..2047 (16B granules)
            int reg = task >> 7;                       // 0..15
            int off = task & 127;
            int lb = reg >> 1, lk = reg & 1;
            uint4* dst = reinterpret_cast<uint4*>(
                Ahp + ((size_t)((m0 >> 4) + lb) * 4 + kt2base + lk) * 256);
            dst[off] = s4[reg * 128 + off];
        }
    } else if (blockIdx.x < 640) {
        // ------- rowsum + adj pack: cp.async double-buffered stream --------
        uint2 (*sm)[32 * 9] = reinterpret_cast<uint2 (*)[32 * 9]>(dyn + 2 * RS_INBUF);

        const int blk  = blockIdx.x - 128;    // 0..511
        const int M0   = blk * 16;
        const int g    = tid >> 5;            // 0..7
        const int lane = tid & 31;

        const int sidx = lane * 9 + (g ^ ((lane & 3) << 1));
        const int ridx = (tid >> 3) * 9 + (tid & 7);
        const uint32_t inb = smem_u32(dyn);

        // issue one round (4 ktiles = 16 rows x 256 cols = 16 KB) into buf
        auto issueR = [&](int ot, int buf) {
#pragma unroll
            for (int i = 0; i < 4; i++) {
                int task = tid + i * 256;      // 0..1023 granules
                int row = task >> 6;
                int off = task & 63;
                const char* s = reinterpret_cast<const char*>(
                    adj + (size_t)(M0 + row) * NN + ot * 256) + (size_t)off * 16;
                CP_ASYNC16(inb + buf * RS_INBUF + task * 16, s);
            }
            CP_COMMIT();
        };

        float s0 = 0.f, s1 = 0.f;

        issueR(0, 0);
        issueR(1, 1);

        for (int ot = 0; ot < 32; ot++) {
            if (ot + 1 < 32) { CP_WAIT1(); } else { CP_WAIT0(); }
            __syncthreads();   // inbuf[ot] visible; prev sm reads done
            const float* inp = reinterpret_cast<const float*>(dyn)
                             + (ot & 1) * 4096;
#pragma unroll
            for (int sub = 0; sub < 4; sub++) {
                float2 a = *reinterpret_cast<const float2*>(
                    inp + g * 256 + sub * 64 + lane * 2);
                float2 b = *reinterpret_cast<const float2*>(
                    inp + (g + 8) * 256 + sub * 64 + lane * 2);
                s0 += a.x + a.y;
                s1 += b.x + b.y;
                uint2 u;
                u.x = pk16(a.y, a.x);
                u.y = pk16(b.y, b.x);
                sm[sub][sidx] = u;
            }
            __syncthreads();   // sm visible; inbuf consumed
            if (ot + 2 < 32) issueR(ot + 2, ot & 1);
#pragma unroll
            for (int sub = 0; sub < 4; sub++)
                Ap[((size_t)blk * 128 + ot * 4 + sub) * 256 + tid] = sm[sub][ridx];
        }

        for (int o = 16; o > 0; o >>= 1) {
            s0 += __shfl_down_sync(0xffffffffu, s0, o);
            s1 += __shfl_down_sync(0xffffffffu, s1, o);
        }
        if (lane == 0) {
            r[M0 + g]     = rsqrtf(s0 + 1.0f);
            r[M0 + g + 8] = rsqrtf(s1 + 1.0f);
        }
    } else {
        // ---------------- W2 -> fp16 B-fragment pack ----------------
        const int K16 = blockIdx.x - 640;     // 0..15
#pragma unroll
        for (int i = 0; i < 8; i++) {
            int idx = tid + i * 256;          // 0..2047
            int n  = idx >> 2;
            int t4 = idx & 3;
            int k0 = K16 * 16 + t4 * 2;
            float2 lo = *reinterpret_cast<const float2*>(&W2[(size_t)n * HID + k0]);
            float2 hi = *reinterpret_cast<const float2*>(&W2[(size_t)n * HID + k0 + 8]);
            uint2 u;
            u.x = pk16(lo.y, lo.x);
            u.y = pk16(hi.y, hi.x);
            Bp2[((size_t)K16 * 512 + n) * 4 + t4] = u;
        }
    }
}

// ---------------------------------------------------------------------------
// gemm2 (fp16): g = rvec[row]*(h1 @ W2^T + b2)   [8192,512], K=256 (KT=4)
// Epilogue writes g as fp16 row-major (half2) + Bp fragments.
// ---------------------------------------------------------------------------
#define G2_S   4
#define G2_AB  16384
#define G2_BB  32768
#define G2_SMEM (G2_S * (G2_AB + G2_BB)) // 192 KB
#define G2_KT  4

__global__ __launch_bounds__(256, 1) void gemm2_fp16(
    const uint2* __restrict__ Ahp, const uint2* __restrict__ Bp2,
    const float* __restrict__ bias, const float* __restrict__ rvec,
    __half* __restrict__ g16, char* __restrict__ BpOut) {

    extern __shared__ __align__(16) char smem[];
    char* smA = smem;
    char* smB = smem + G2_S * G2_AB;

    const int tid  = threadIdx.x;
    const int lane = tid & 31;
    const int wid  = tid >> 5;
    const int wm = wid >> 2;
    const int wn = wid & 3;
    const int m0 = blockIdx.y * 128;
    const int n0 = blockIdx.x * 256;
    const int blk16base = m0 >> 4;

    const char* ApB = reinterpret_cast<const char*>(Ahp);
    const char* BpB = reinterpret_cast<const char*>(Bp2);

    auto issue = [&](int kt, int slot) {
        uint32_t dA = smem_u32(smA + slot * G2_AB);
        uint32_t dB = smem_u32(smB + slot * G2_BB);
#pragma unroll
        for (int i = 0; i < 4; i++) {
            int task = tid + i * 256;
            int blk = task >> 7;
            int off = task & 127;
            const char* s = ApB + ((size_t)(blk16base + blk) * G2_KT + kt) * 2048
                          + (size_t)off * 16;
            CP_ASYNC16(dA + task * 16, s);
        }
#pragma unroll
        for (int i = 0; i < 8; i++) {
            int task = tid + i * 256;
            int ks  = task >> 9;
            int off = task & 511;
            const char* s = BpB + ((size_t)(kt * 4 + ks) * 512 + n0) * 32
                          + (size_t)off * 16;
            CP_ASYNC16(dB + task * 16, s);
        }
        CP_COMMIT();
    };

    float acc[4][8][4];
#pragma unroll
    for (int mi = 0; mi < 4; mi++)
#pragma unroll
        for (int nj = 0; nj < 8; nj++)
#pragma unroll
            for (int q = 0; q < 4; q++) acc[mi][nj][q] = 0.f;

    issue(0, 0);
    issue(1, 1);
    issue(2, 2);

    const int g8 = lane >> 2;
    const int t4 = lane & 3;
    const int axor = g8 ^ (t4 << 1);

    for (int kt = 0; kt < G2_KT; kt++) {
        const int slot = kt & 3;
        const int rem = G2_KT - 1 - kt;
        if (rem >= 2)      { CP_WAIT2(); }
        else if (rem == 1) { CP_WAIT1(); }
        else               { CP_WAIT0(); }
        __syncthreads();
        if (kt + 3 < G2_KT) issue(kt + 3, (kt + 3) & 3);

        const char* Ab = smA + slot * G2_AB;
        const char* Bb = smB + slot * G2_BB;

#pragma unroll
        for (int ks = 0; ks < 4; ks++) {
            uint32_t af[4][4];
#pragma unroll
            for (int mi = 0; mi < 4; mi++) {
                int blk = wm * 4 + mi;
                const char* p = Ab
                    + (size_t)(blk * 256 + (ks * 8 + t4) * 8 + axor) * 8;
                uint2 xx = *reinterpret_cast<const uint2*>(p);
                uint2 yy = *reinterpret_cast<const uint2*>(p + 256);
                af[mi][0] = xx.x; af[mi][1] = xx.y;
                af[mi][2] = yy.x; af[mi][3] = yy.y;
            }
            uint32_t bf[8][2];
#pragma unroll
            for (int nj = 0; nj < 8; nj++) {
                const char* p = Bb
                    + (size_t)(((ks * 256 + wn * 64 + nj * 8 + g8) * 4) + t4) * 8;
                uint2 xx = *reinterpret_cast<const uint2*>(p);
                bf[nj][0] = xx.x; bf[nj][1] = xx.y;
            }
#pragma unroll
            for (int mi = 0; mi < 4; mi++)
#pragma unroll
                for (int nj = 0; nj < 8; nj++)
                    mma_fp16(acc[mi][nj], af[mi], bf[nj]);
        }
    }

    // epilogue: g = rv*(acc + bias) -> fp16 (half2 store) + Bp fragments
#pragma unroll
    for (int mi = 0; mi < 4; mi++) {
#pragma unroll
        for (int h = 0; h < 2; h++) {
            int row = m0 + wm * 64 + mi * 16 + g8 + h * 8;
            float rv = rvec[row];
            __half* gp = g16 + (size_t)row * OUTF;
#pragma unroll
            for (int nj = 0; nj < 8; nj++) {
                int col = n0 + wn * 64 + nj * 8 + t4 * 2;
                float ox = rv * (acc[mi][nj][h * 2 + 0] + bias[col]);
                float oy = rv * (acc[mi][nj][h * 2 + 1] + bias[col + 1]);
                uint32_t packed = pk16(oy, ox);
                *reinterpret_cast<uint32_t*>(gp + col) = packed;
                size_t ub = ((size_t)(row >> 4) * 512 + col) * 32
                          + (size_t)(g8 >> 1) * 8 + (h ? 4 : 0) + (g8 & 1) * 2;
                *reinterpret_cast<__half*>(BpOut + ub) =
                    __ushort_as_half((unsigned short)(packed & 0xFFFF));
                *reinterpret_cast<__half*>(BpOut + ub + 32) =
                    __ushort_as_half((unsigned short)(packed >> 16));
            }
        }
    }
}

// ---------------------------------------------------------------------------
// GEMM3 (fp16): out = diag(r) * (adj @ g + g)   [8192x512], K=8192
// CTA 128m x 256n, warp grid 2m x 4n (warp 64x64), 4 stages,
// 2 ktiles per barrier round, issues split around the first compute.
// ---------------------------------------------------------------------------
#define G3_S   4
#define G3_AB  16384
#define G3_BB  32768
#define G3_SMEM (G3_S * (G3_AB + G3_BB)) // 192 KB
#define G3_KT  (NN / 64)                 // 128

__global__ __launch_bounds__(256, 1) void gemm3_fp16(
    const uint2* __restrict__ Ap, const uint4* __restrict__ Bp,
    const __half* __restrict__ g16, const float* __restrict__ rvec,
    float* __restrict__ out) {

    extern __shared__ __align__(16) char smem[];
    char* smA = smem;
    char* smB = smem + G3_S * G3_AB;

    const int tid  = threadIdx.x;
    const int lane = tid & 31;
    const int wid  = tid >> 5;
    const int wm = wid >> 2;
    const int wn = wid & 3;
    const int m0 = blockIdx.y * 128;
    const int n0 = blockIdx.x * 256;
    const int blk16base = m0 >> 4;

    const char* ApB = reinterpret_cast<const char*>(Ap);
    const char* BpB = reinterpret_cast<const char*>(Bp);

    auto issue = [&](int kt, int slot) {
        uint32_t dA = smem_u32(smA + slot * G3_AB);
        uint32_t dB = smem_u32(smB + slot * G3_BB);
#pragma unroll
        for (int i = 0; i < 4; i++) {
            int task = tid + i * 256;
            int blk = task >> 7;
            int off = task & 127;
            const char* s = ApB + ((size_t)(blk16base + blk) * 128 + kt) * 2048
                          + (size_t)off * 16;
            CP_ASYNC16(dA + task * 16, s);
        }
#pragma unroll
        for (int i = 0; i < 8; i++) {
            int task = tid + i * 256;
            int ks  = task >> 9;
            int off = task & 511;
            const char* s = BpB + ((size_t)(kt * 4 + ks) * 512 + n0) * 32
                          + (size_t)off * 16;
            CP_ASYNC16(dB + task * 16, s);
        }
        CP_COMMIT();
    };

    float acc[4][8][4];
#pragma unroll
    for (int mi = 0; mi < 4; mi++)
#pragma unroll
        for (int nj = 0; nj < 8; nj++)
#pragma unroll
            for (int q = 0; q < 4; q++) acc[mi][nj][q] = 0.f;

    // prologue: stages 0,1 in flight
    issue(0, 0);
    issue(1, 1);

    const int g8 = lane >> 2;
    const int t4 = lane & 3;
    const int axor = g8 ^ (t4 << 1);

    auto compute_ktile = [&](const char* Ab, const char* Bb) {
#pragma unroll
        for (int ks = 0; ks < 4; ks++) {
            uint32_t af[4][4];
#pragma unroll
            for (int mi = 0; mi < 4; mi++) {
                int blk = wm * 4 + mi;
                const char* p = Ab
                    + (size_t)(blk * 256 + (ks * 8 + t4) * 8 + axor) * 8;
                uint2 xx = *reinterpret_cast<const uint2*>(p);
                uint2 yy = *reinterpret_cast<const uint2*>(p + 256);
                af[mi][0] = xx.x; af[mi][1] = xx.y;
                af[mi][2] = yy.x; af[mi][3] = yy.y;
            }
            uint32_t bf[8][2];
#pragma unroll
            for (int nj = 0; nj < 8; nj++) {
                const char* p = Bb
                    + (size_t)(((ks * 256 + wn * 64 + nj * 8 + g8) * 4) + t4) * 8;
                uint2 xx = *reinterpret_cast<const uint2*>(p);
                bf[nj][0] = xx.x; bf[nj][1] = xx.y;
            }
#pragma unroll
            for (int mi = 0; mi < 4; mi++)
#pragma unroll
                for (int nj = 0; nj < 8; nj++)
                    mma_fp16(acc[mi][nj], af[mi], bf[nj]);
        }
    };

    for (int kt = 0; kt < G3_KT; kt += 2) {
        CP_WAIT0();
        __syncthreads();   // visibility + protects slots (kt+2)&3,(kt+3)&3
        if (kt + 2 < G3_KT) issue(kt + 2, (kt + 2) & 3);
        compute_ktile(smA + (kt & 3) * G3_AB, smB + (kt & 3) * G3_BB);
        if (kt + 3 < G3_KT) issue(kt + 3, (kt + 3) & 3);
        compute_ktile(smA + ((kt + 1) & 3) * G3_AB, smB + ((kt + 1) & 3) * G3_BB);
    }

    // epilogue: out = r * (acc + g)   (g read as fp16 half2)
#pragma unroll
    for (int mi = 0; mi < 4; mi++) {
#pragma unroll
        for (int h = 0; h < 2; h++) {
            int row = m0 + wm * 64 + mi * 16 + g8 + h * 8;
            float rv = rvec[row];
            const __half* gp = g16 + (size_t)row * OUTF;
            float* op = out + (size_t)row * OUTF;
#pragma unroll
            for (int nj = 0; nj < 8; nj++) {
                int col = n0 + wn * 64 + nj * 8 + t4 * 2;
                __half2 gv = *reinterpret_cast<const __half2*>(gp + col);
                float2 gf = __half22float2(gv);
                float2 o;
                o.x = rv * (acc[mi][nj][h * 2 + 0] + gf.x);
                o.y = rv * (acc[mi][nj][h * 2 + 1] + gf.y);
                *reinterpret_cast<float2*>(op + col) = o;
            }
        }
    }
}

// ---------------------------------------------------------------------------
extern "C" void kernel_launch(void* const* d_in, const int* in_sizes, int n_in,
                              void* d_out, int out_size) {
    const float* x   = (const float*)d_in[0];
    const float* adj = (const float*)d_in[1];
    const float* W1  = (const float*)d_in[2];
    const float* b1  = (const float*)d_in[3];
    const float* W2  = (const float*)d_in[4];
    const float* b2  = (const float*)d_in[5];
    float* out = (float*)d_out;

    float* rp;
    __half* g16p;
    uint4* Bpp;
    uint2 *App, *Ahpp, *Bp2p;
    cudaGetSymbolAddress((void**)&g16p, g_g16);
    cudaGetSymbolAddress((void**)&Bpp, g_Bp);
    cudaGetSymbolAddress((void**)&App, g_Ap);
    cudaGetSymbolAddress((void**)&Ahpp, g_Ahp);
    cudaGetSymbolAddress((void**)&Bp2p, g_Bp2);
    cudaGetSymbolAddress((void**)&rp, g_r);

    cudaFuncSetAttribute(fused_pre, cudaFuncAttributeMaxDynamicSharedMemorySize,
                         PRE_SMEM);
    cudaFuncSetAttribute(gemm2_fp16, cudaFuncAttributeMaxDynamicSharedMemorySize,
                         G2_SMEM);
    cudaFuncSetAttribute(gemm3_fp16, cudaFuncAttributeMaxDynamicSharedMemorySize,
                         G3_SMEM);

    // gemm1 || rowsum+pack (cp.async) || W2 pack
    fused_pre<<<656, 256, PRE_SMEM>>>(adj, rp, App, x, W1, Ahpp, b1, W2, Bp2p);
    // g = r ⊙ (h1 @ W2^T + b2)  (fp16 MMA) -> g16 + Bp
    gemm2_fp16<<<dim3(2, 64), 256, G2_SMEM>>>(Ahpp, Bp2p, b2, rp, g16p, (char*)Bpp);
    // out = diag(r) * (adj @ g + g)  (fp16 MMA, 2 ktiles per barrier)
    gemm3_fp16<<<dim3(2, 64), 256, G3_SMEM>>>(App, Bpp, g16p, rp, out);
}

// round 17
// speedup vs baseline: 1.0377x; 1.0377x over previous
#include <cuda_runtime.h>
#include <cuda_fp16.h>
#include <cstdint>

// ---------------------------------------------------------------------------
// GCN layer:  out = D^-1/2 (adj+I) D^-1/2 @ ((x@W1^T+b1)@W2^T + b2)
// Folded:  r = rsqrt(rowsum(adj)+1); h1 = x@W1^T+b1;
//          g = r ⊙ (h1@W2^T+b2);     out = diag(r) * (adj@g + g)
// Chain (3 kernels)  — R15 configuration (best measured: 260.5 us):
//   fused_pre : [0,128) gemm1 tf32 -> Ahp, [128,640) rowsum + adj pack
//               (register-staged MLP-8 loop), [640,656) W2 pack
//   gemm2     : fp16 m16n8k16 (KT=4); writes g fp16 + Bp fragments
//   gemm3     : fp16 m16n8k16, CTA 128x256, warp 64x64, 4 stages,
//               2 ktiles per barrier round, split issue placement
// ---------------------------------------------------------------------------

#define NN   8192
#define HID  256
#define OUTF 512

__device__ __half g_g16[NN * OUTF];      // 8 MB  g (fp16, row-major)
__device__ uint4 g_Bp[512 * 512 * 2];    // 8 MB  g fragment-packed fp16 (gemm3 B)
__device__ uint2 g_Ap[512 * 128 * 256];  // 128 MB adj A-fragments fp16
__device__ uint2 g_Ahp[512 * 4 * 256];   // 4 MB  h1 A-fragments fp16 (gemm2 A)
__device__ uint2 g_Bp2[16 * 512 * 4];    // 256 KB W2 B-fragments fp16 (gemm2 B)
__device__ float g_r[NN];

__device__ __forceinline__ uint32_t f2tf(float f) {
    uint32_t u;
    asm("cvt.rna.tf32.f32 %0, %1;" : "=r"(u) : "f"(f));
    return u;
}
// pack {lo, hi} floats into f16x2 (lo in bits[15:0])
__device__ __forceinline__ uint32_t pk16(float hi, float lo) {
    uint32_t u;
    asm("cvt.rn.f16x2.f32 %0, %1, %2;" : "=r"(u) : "f"(hi), "f"(lo));
    return u;
}
__device__ __forceinline__ uint32_t smem_u32(const void* p) {
    uint32_t a;
    asm("{ .reg .u64 t; cvta.to.shared.u64 t, %1; cvt.u32.u64 %0, t; }"
        : "=r"(a) : "l"(p));
    return a;
}
__device__ __forceinline__ void mma_tf32(float* c, const uint32_t* a,
                                         uint32_t b0, uint32_t b1) {
    asm volatile(
        "mma.sync.aligned.m16n8k8.row.col.f32.tf32.tf32.f32 "
        "{%0,%1,%2,%3},{%4,%5,%6,%7},{%8,%9},{%0,%1,%2,%3};"
        : "+f"(c[0]), "+f"(c[1]), "+f"(c[2]), "+f"(c[3])
        : "r"(a[0]), "r"(a[1]), "r"(a[2]), "r"(a[3]), "r"(b0), "r"(b1));
}
__device__ __forceinline__ void mma_fp16(float* c, const uint32_t* a,
                                         const uint32_t* b) {
    asm volatile(
        "mma.sync.aligned.m16n8k16.row.col.f32.f16.f16.f32 "
        "{%0,%1,%2,%3},{%4,%5,%6,%7},{%8,%9},{%0,%1,%2,%3};"
        : "+f"(c[0]), "+f"(c[1]), "+f"(c[2]), "+f"(c[3])
        : "r"(a[0]), "r"(a[1]), "r"(a[2]), "r"(a[3]), "r"(b[0]), "r"(b[1]));
}

#define CP_ASYNC16(dst, src) \
    asm volatile("cp.async.cg.shared.global [%0], [%1], 16;" \
                 :: "r"(dst), "l"(src) : "memory")
#define CP_COMMIT() asm volatile("cp.async.commit_group;" ::: "memory")
#define CP_WAIT0()  asm volatile("cp.async.wait_group 0;" ::: "memory")
#define CP_WAIT1()  asm volatile("cp.async.wait_group 1;" ::: "memory")
#define CP_WAIT2()  asm volatile("cp.async.wait_group 2;" ::: "memory")

// ---------------------------------------------------------------------------
// fused_pre (656 blocks, 256 threads):
//   [0,128)   gemm1: h1 = x@W1^T + b1 -> fp16 A-fragment units into Ahp
//             (fragments staged in smem, then coalesced uint4 gmem stores)
//   [128,640) rowsum r + adj -> fp16 A-fragment units into Ap
//             (R7 loop: 4 subtiles per sync round, 8 loads in flight)
//   [640,656) W2 -> fp16 B-fragment units into Bp2
// A-fragment unit (uint2): { f16x2(row g, k..k+1), f16x2(row g+8, k..k+1) }
//   at index ((blk16*KT + kt)*256 + kpl*8 + gx),
//   kpl=(k%64)/2, gx = g ^ ((kpl&3)<<1).  Ap: KT=128, Ahp: KT=4.
// ---------------------------------------------------------------------------
#define PRE_SMEM (2 * 128 * 36 * 4)     // 36864 (gemm1 branch is the max)

__global__ __launch_bounds__(256) void fused_pre(
    const float* __restrict__ adj, float* __restrict__ r, uint2* __restrict__ Ap,
    const float* __restrict__ x, const float* __restrict__ W1,
    uint2* __restrict__ Ahp, const float* __restrict__ b1,
    const float* __restrict__ W2, uint2* __restrict__ Bp2) {

    extern __shared__ __align__(16) char dyn[];
    const int tid = threadIdx.x;

    if (blockIdx.x < 128) {
        // ---------------- gemm1 (tf32), epilogue -> Ahp fragments ----------
        const int K_ = 512;
        float* As = reinterpret_cast<float*>(dyn);
        float* Bs = As + 128 * 36;

        const int lane = tid & 31;
        const int warp = tid >> 5;
        const int wm = warp >> 1;
        const int wn = warp & 1;
        const int bx = blockIdx.x;
        const int m0 = (bx >> 1) * 128;
        const int n0 = (bx & 1) * 128;
        const int KT = K_ / 32;

        float acc[2][8][4];
#pragma unroll
        for (int mi = 0; mi < 2; mi++)
#pragma unroll
            for (int nj = 0; nj < 8; nj++)
#pragma unroll
                for (int q = 0; q < 4; q++) acc[mi][nj][q] = 0.f;

        float4 pa[4], pb[4];

        auto loadA = [&](int kt, float4* p) {
#pragma unroll
            for (int i = 0; i < 4; i++) {
                int idx = tid + i * 256;
                int row = idx >> 3;
                int kc  = (idx & 7) << 2;
                p[i] = *reinterpret_cast<const float4*>(
                    &x[(size_t)(m0 + row) * K_ + kt * 32 + kc]);
            }
        };
        auto storeA = [&](const float4* p) {
#pragma unroll
            for (int i = 0; i < 4; i++) {
                int idx = tid + i * 256;
                int row = idx >> 3;
                int kc  = (idx & 7) << 2;
                uint4 t = make_uint4(f2tf(p[i].x), f2tf(p[i].y),
                                     f2tf(p[i].z), f2tf(p[i].w));
                *reinterpret_cast<uint4*>(&As[row * 36 + kc]) = t;
            }
        };
        auto loadB = [&](int kt, float4* p) {
#pragma unroll
            for (int i = 0; i < 4; i++) {
                int idx = tid + i * 256;
                int row = idx >> 3;
                int kc  = (idx & 7) << 2;
                p[i] = *reinterpret_cast<const float4*>(
                    &W1[(size_t)(n0 + row) * K_ + kt * 32 + kc]);
            }
        };
        auto storeB = [&](const float4* p) {
#pragma unroll
            for (int i = 0; i < 4; i++) {
                int idx = tid + i * 256;
                int row = idx >> 3;
                int kc  = (idx & 7) << 2;
                uint4 t = make_uint4(f2tf(p[i].x), f2tf(p[i].y),
                                     f2tf(p[i].z), f2tf(p[i].w));
                *reinterpret_cast<uint4*>(&Bs[row * 36 + kc]) = t;
            }
        };

        loadA(0, pa); loadB(0, pb);
        storeA(pa);   storeB(pb);
        __syncthreads();

        for (int kt = 0; kt < KT; kt++) {
            if (kt + 1 < KT) { loadA(kt + 1, pa); loadB(kt + 1, pb); }
#pragma unroll
            for (int kk = 0; kk < 4; kk++) {
                uint32_t afr[2][4];
#pragma unroll
                for (int mi = 0; mi < 2; mi++) {
                    int r0 = wm * 32 + mi * 16 + (lane >> 2);
                    int kb = kk * 8 + (lane & 3);
                    afr[mi][0] = __float_as_uint(As[r0 * 36 + kb]);
                    afr[mi][1] = __float_as_uint(As[(r0 + 8) * 36 + kb]);
                    afr[mi][2] = __float_as_uint(As[r0 * 36 + kb + 4]);
                    afr[mi][3] = __float_as_uint(As[(r0 + 8) * 36 + kb + 4]);
                }
#pragma unroll
                for (int nj = 0; nj < 8; nj++) {
                    int nn = wn * 64 + nj * 8 + (lane >> 2);
                    int k0 = kk * 8 + (lane & 3);
                    uint32_t b0 = __float_as_uint(Bs[nn * 36 + k0]);
                    uint32_t b1_ = __float_as_uint(Bs[nn * 36 + k0 + 4]);
                    mma_tf32(acc[0][nj], afr[0], b0, b1_);
                    mma_tf32(acc[1][nj], afr[1], b0, b1_);
                }
            }
            __syncthreads();
            if (kt + 1 < KT) {
                storeA(pa); storeB(pb);
                __syncthreads();
            }
        }

        // epilogue: scatter fragments into smem, then coalesced uint4 stores.
        uint2* stg = reinterpret_cast<uint2*>(dyn);   // 16 regions x 256 units
        const int lr  = lane >> 2;
        const int lc2 = (lane & 3) * 2;
#pragma unroll
        for (int mi = 0; mi < 2; mi++) {
#pragma unroll
            for (int nj = 0; nj < 8; nj++) {
                int rowl = wm * 32 + mi * 16 + lr;     // local row 0..127
                int coll = wn * 64 + nj * 8 + lc2;     // local col 0..127
                int col  = n0 + coll;
                const float* cc = acc[mi][nj];
                uint2 u;
                u.x = pk16(cc[1] + b1[col + 1], cc[0] + b1[col]);  // row
                u.y = pk16(cc[3] + b1[col + 1], cc[2] + b1[col]);  // row+8
                int lb  = rowl >> 4;                   // 0..7
                int lk  = coll >> 6;                   // 0..1
                int kpl = (coll & 63) >> 1;
                int gx  = lr ^ ((kpl & 3) << 1);
                stg[(lb * 2 + lk) * 256 + kpl * 8 + gx] = u;
            }
        }
        __syncthreads();
        const int kt2base = n0 >> 6;
        const uint4* s4 = reinterpret_cast<const uint4*>(dyn);
#pragma unroll
        for (int i = 0; i < 8; i++) {
            int task = tid + i * 256;                  // 0..2047 (16B granules)
            int reg = task >> 7;                       // 0..15
            int off = task & 127;
            int lb = reg >> 1, lk = reg & 1;
            uint4* dst = reinterpret_cast<uint4*>(
                Ahp + ((size_t)((m0 >> 4) + lb) * 4 + kt2base + lk) * 256);
            dst[off] = s4[reg * 128 + off];
        }
    } else if (blockIdx.x < 640) {
        // ------- rowsum + adj pack: R7 loop (4 subs / sync round) ----------
        uint2 (*sm)[32 * 9] = reinterpret_cast<uint2 (*)[32 * 9]>(dyn);

        const int blk  = blockIdx.x - 128;    // 0..511
        const int M0   = blk * 16;
        const int g    = tid >> 5;            // 0..7
        const int lane = tid & 31;

        const float2* p0 = reinterpret_cast<const float2*>(
            adj + (size_t)(M0 + g) * NN) + lane;
        const float2* p1 = reinterpret_cast<const float2*>(
            adj + (size_t)(M0 + g + 8) * NN) + lane;

        const int sidx = lane * 9 + (g ^ ((lane & 3) << 1));
        const int ridx = (tid >> 3) * 9 + (tid & 7);

        float s0 = 0.f, s1 = 0.f;

        for (int ot = 0; ot < 32; ot++) {
            float2 c0[4], c1[4];
#pragma unroll
            for (int sub = 0; sub < 4; sub++) {
                c0[sub] = p0[(ot * 4 + sub) * 32];
                c1[sub] = p1[(ot * 4 + sub) * 32];
            }
#pragma unroll
            for (int sub = 0; sub < 4; sub++) {
                s0 += c0[sub].x + c0[sub].y;
                s1 += c1[sub].x + c1[sub].y;
                uint2 u;
                u.x = pk16(c0[sub].y, c0[sub].x);
                u.y = pk16(c1[sub].y, c1[sub].x);
                sm[sub][sidx] = u;
            }
            __syncthreads();
#pragma unroll
            for (int sub = 0; sub < 4; sub++)
                Ap[((size_t)blk * 128 + ot * 4 + sub) * 256 + tid] = sm[sub][ridx];
            __syncthreads();
        }

        for (int o = 16; o > 0; o >>= 1) {
            s0 += __shfl_down_sync(0xffffffffu, s0, o);
            s1 += __shfl_down_sync(0xffffffffu, s1, o);
        }
        if (lane == 0) {
            r[M0 + g]     = rsqrtf(s0 + 1.0f);
            r[M0 + g + 8] = rsqrtf(s1 + 1.0f);
        }
    } else {
        // ---------------- W2 -> fp16 B-fragment pack ----------------
        const int K16 = blockIdx.x - 640;     // 0..15
#pragma unroll
        for (int i = 0; i < 8; i++) {
            int idx = tid + i * 256;          // 0..2047
            int n  = idx >> 2;
            int t4 = idx & 3;
            int k0 = K16 * 16 + t4 * 2;
            float2 lo = *reinterpret_cast<const float2*>(&W2[(size_t)n * HID + k0]);
            float2 hi = *reinterpret_cast<const float2*>(&W2[(size_t)n * HID + k0 + 8]);
            uint2 u;
            u.x = pk16(lo.y, lo.x);
            u.y = pk16(hi.y, hi.x);
            Bp2[((size_t)K16 * 512 + n) * 4 + t4] = u;
        }
    }
}

// ---------------------------------------------------------------------------
// gemm2 (fp16): g = rvec[row]*(h1 @ W2^T + b2)   [8192,512], K=256 (KT=4)
// Epilogue writes g as fp16 row-major (half2) + Bp fragments.
// ---------------------------------------------------------------------------
#define G2_S   4
#define G2_AB  16384
#define G2_BB  32768
#define G2_SMEM (G2_S * (G2_AB + G2_BB)) // 192 KB
#define G2_KT  4

__global__ __launch_bounds__(256, 1) void gemm2_fp16(
    const uint2* __restrict__ Ahp, const uint2* __restrict__ Bp2,
    const float* __restrict__ bias, const float* __restrict__ rvec,
    __half* __restrict__ g16, char* __restrict__ BpOut) {

    extern __shared__ __align__(16) char smem[];
    char* smA = smem;
    char* smB = smem + G2_S * G2_AB;

    const int tid  = threadIdx.x;
    const int lane = tid & 31;
    const int wid  = tid >> 5;
    const int wm = wid >> 2;
    const int wn = wid & 3;
    const int m0 = blockIdx.y * 128;
    const int n0 = blockIdx.x * 256;
    const int blk16base = m0 >> 4;

    const char* ApB = reinterpret_cast<const char*>(Ahp);
    const char* BpB = reinterpret_cast<const char*>(Bp2);

    auto issue = [&](int kt, int slot) {
        uint32_t dA = smem_u32(smA + slot * G2_AB);
        uint32_t dB = smem_u32(smB + slot * G2_BB);
#pragma unroll
        for (int i = 0; i < 4; i++) {
            int task = tid + i * 256;
            int blk = task >> 7;
            int off = task & 127;
            const char* s = ApB + ((size_t)(blk16base + blk) * G2_KT + kt) * 2048
                          + (size_t)off * 16;
            CP_ASYNC16(dA + task * 16, s);
        }
#pragma unroll
        for (int i = 0; i < 8; i++) {
            int task = tid + i * 256;
            int ks  = task >> 9;
            int off = task & 511;
            const char* s = BpB + ((size_t)(kt * 4 + ks) * 512 + n0) * 32
                          + (size_t)off * 16;
            CP_ASYNC16(dB + task * 16, s);
        }
        CP_COMMIT();
    };

    float acc[4][8][4];
#pragma unroll
    for (int mi = 0; mi < 4; mi++)
#pragma unroll
        for (int nj = 0; nj < 8; nj++)
#pragma unroll
            for (int q = 0; q < 4; q++) acc[mi][nj][q] = 0.f;

    issue(0, 0);
    issue(1, 1);
    issue(2, 2);

    const int g8 = lane >> 2;
    const int t4 = lane & 3;
    const int axor = g8 ^ (t4 << 1);

    for (int kt = 0; kt < G2_KT; kt++) {
        const int slot = kt & 3;
        const int rem = G2_KT - 1 - kt;
        if (rem >= 2)      { CP_WAIT2(); }
        else if (rem == 1) { CP_WAIT1(); }
        else               { CP_WAIT0(); }
        __syncthreads();
        if (kt + 3 < G2_KT) issue(kt + 3, (kt + 3) & 3);

        const char* Ab = smA + slot * G2_AB;
        const char* Bb = smB + slot * G2_BB;

#pragma unroll
        for (int ks = 0; ks < 4; ks++) {
            uint32_t af[4][4];
#pragma unroll
            for (int mi = 0; mi < 4; mi++) {
                int blk = wm * 4 + mi;
                const char* p = Ab
                    + (size_t)(blk * 256 + (ks * 8 + t4) * 8 + axor) * 8;
                uint2 xx = *reinterpret_cast<const uint2*>(p);
                uint2 yy = *reinterpret_cast<const uint2*>(p + 256);
                af[mi][0] = xx.x; af[mi][1] = xx.y;
                af[mi][2] = yy.x; af[mi][3] = yy.y;
            }
            uint32_t bf[8][2];
#pragma unroll
            for (int nj = 0; nj < 8; nj++) {
                const char* p = Bb
                    + (size_t)(((ks * 256 + wn * 64 + nj * 8 + g8) * 4) + t4) * 8;
                uint2 xx = *reinterpret_cast<const uint2*>(p);
                bf[nj][0] = xx.x; bf[nj][1] = xx.y;
            }
#pragma unroll
            for (int mi = 0; mi < 4; mi++)
#pragma unroll
                for (int nj = 0; nj < 8; nj++)
                    mma_fp16(acc[mi][nj], af[mi], bf[nj]);
        }
    }

    // epilogue: g = rv*(acc + bias) -> fp16 (half2 store) + Bp fragments
#pragma unroll
    for (int mi = 0; mi < 4; mi++) {
#pragma unroll
        for (int h = 0; h < 2; h++) {
            int row = m0 + wm * 64 + mi * 16 + g8 + h * 8;
            float rv = rvec[row];
            __half* gp = g16 + (size_t)row * OUTF;
#pragma unroll
            for (int nj = 0; nj < 8; nj++) {
                int col = n0 + wn * 64 + nj * 8 + t4 * 2;
                float ox = rv * (acc[mi][nj][h * 2 + 0] + bias[col]);
                float oy = rv * (acc[mi][nj][h * 2 + 1] + bias[col + 1]);
                uint32_t packed = pk16(oy, ox);
                *reinterpret_cast<uint32_t*>(gp + col) = packed;
                size_t ub = ((size_t)(row >> 4) * 512 + col) * 32
                          + (size_t)(g8 >> 1) * 8 + (h ? 4 : 0) + (g8 & 1) * 2;
                *reinterpret_cast<__half*>(BpOut + ub) =
                    __ushort_as_half((unsigned short)(packed & 0xFFFF));
                *reinterpret_cast<__half*>(BpOut + ub + 32) =
                    __ushort_as_half((unsigned short)(packed >> 16));
            }
        }
    }
}

// ---------------------------------------------------------------------------
// GEMM3 (fp16): out = diag(r) * (adj @ g + g)   [8192x512], K=8192
// CTA 128m x 256n, warp grid 2m x 4n (warp 64x64), 4 stages,
// 2 ktiles per barrier round, issues split around the first compute.
// Epilogue reads g from fp16 buffer (half2).
// ---------------------------------------------------------------------------
#define G3_S   4
#define G3_AB  16384
#define G3_BB  32768
#define G3_SMEM (G3_S * (G3_AB + G3_BB)) // 192 KB
#define G3_KT  (NN / 64)                 // 128

__global__ __launch_bounds__(256, 1) void gemm3_fp16(
    const uint2* __restrict__ Ap, const uint4* __restrict__ Bp,
    const __half* __restrict__ g16, const float* __restrict__ rvec,
    float* __restrict__ out) {

    extern __shared__ __align__(16) char smem[];
    char* smA = smem;
    char* smB = smem + G3_S * G3_AB;

    const int tid  = threadIdx.x;
    const int lane = tid & 31;
    const int wid  = tid >> 5;
    const int wm = wid >> 2;
    const int wn = wid & 3;
    const int m0 = blockIdx.y * 128;
    const int n0 = blockIdx.x * 256;
    const int blk16base = m0 >> 4;

    const char* ApB = reinterpret_cast<const char*>(Ap);
    const char* BpB = reinterpret_cast<const char*>(Bp);

    auto issue = [&](int kt, int slot) {
        uint32_t dA = smem_u32(smA + slot * G3_AB);
        uint32_t dB = smem_u32(smB + slot * G3_BB);
#pragma unroll
        for (int i = 0; i < 4; i++) {
            int task = tid + i * 256;
            int blk = task >> 7;
            int off = task & 127;
            const char* s = ApB + ((size_t)(blk16base + blk) * 128 + kt) * 2048
                          + (size_t)off * 16;
            CP_ASYNC16(dA + task * 16, s);
        }
#pragma unroll
        for (int i = 0; i < 8; i++) {
            int task = tid + i * 256;
            int ks  = task >> 9;
            int off = task & 511;
            const char* s = BpB + ((size_t)(kt * 4 + ks) * 512 + n0) * 32
                          + (size_t)off * 16;
            CP_ASYNC16(dB + task * 16, s);
        }
        CP_COMMIT();
    };

    float acc[4][8][4];
#pragma unroll
    for (int mi = 0; mi < 4; mi++)
#pragma unroll
        for (int nj = 0; nj < 8; nj++)
#pragma unroll
            for (int q = 0; q < 4; q++) acc[mi][nj][q] = 0.f;

    // prologue: stages 0,1 in flight
    issue(0, 0);
    issue(1, 1);

    const int g8 = lane >> 2;
    const int t4 = lane & 3;
    const int axor = g8 ^ (t4 << 1);

    auto compute_ktile = [&](const char* Ab, const char* Bb) {
#pragma unroll
        for (int ks = 0; ks < 4; ks++) {
            uint32_t af[4][4];
#pragma unroll
            for (int mi = 0; mi < 4; mi++) {
                int blk = wm * 4 + mi;
                const char* p = Ab
                    + (size_t)(blk * 256 + (ks * 8 + t4) * 8 + axor) * 8;
                uint2 xx = *reinterpret_cast<const uint2*>(p);
                uint2 yy = *reinterpret_cast<const uint2*>(p + 256);
                af[mi][0] = xx.x; af[mi][1] = xx.y;
                af[mi][2] = yy.x; af[mi][3] = yy.y;
            }
            uint32_t bf[8][2];
#pragma unroll
            for (int nj = 0; nj < 8; nj++) {
                const char* p = Bb
                    + (size_t)(((ks * 256 + wn * 64 + nj * 8 + g8) * 4) + t4) * 8;
                uint2 xx = *reinterpret_cast<const uint2*>(p);
                bf[nj][0] = xx.x; bf[nj][1] = xx.y;
            }
#pragma unroll
            for (int mi = 0; mi < 4; mi++)
#pragma unroll
                for (int nj = 0; nj < 8; nj++)
                    mma_fp16(acc[mi][nj], af[mi], bf[nj]);
        }
    };

    for (int kt = 0; kt < G3_KT; kt += 2) {
        CP_WAIT0();
        __syncthreads();   // visibility + protects slots (kt+2)&3,(kt+3)&3
        if (kt + 2 < G3_KT) issue(kt + 2, (kt + 2) & 3);
        compute_ktile(smA + (kt & 3) * G3_AB, smB + (kt & 3) * G3_BB);
        if (kt + 3 < G3_KT) issue(kt + 3, (kt + 3) & 3);
        compute_ktile(smA + ((kt + 1) & 3) * G3_AB, smB + ((kt + 1) & 3) * G3_BB);
    }

    // epilogue: out = r * (acc + g)   (g read as fp16 half2)
#pragma unroll
    for (int mi = 0; mi < 4; mi++) {
#pragma unroll
        for (int h = 0; h < 2; h++) {
            int row = m0 + wm * 64 + mi * 16 + g8 + h * 8;
            float rv = rvec[row];
            const __half* gp = g16 + (size_t)row * OUTF;
            float* op = out + (size_t)row * OUTF;
#pragma unroll
            for (int nj = 0; nj < 8; nj++) {
                int col = n0 + wn * 64 + nj * 8 + t4 * 2;
                __half2 gv = *reinterpret_cast<const __half2*>(gp + col);
                float2 gf = __half22float2(gv);
                float2 o;
                o.x = rv * (acc[mi][nj][h * 2 + 0] + gf.x);
                o.y = rv * (acc[mi][nj][h * 2 + 1] + gf.y);
                *reinterpret_cast<float2*>(op + col) = o;
            }
        }
    }
}

// ---------------------------------------------------------------------------
extern "C" void kernel_launch(void* const* d_in, const int* in_sizes, int n_in,
                              void* d_out, int out_size) {
    const float* x   = (const float*)d_in[0];
    const float* adj = (const float*)d_in[1];
    const float* W1  = (const float*)d_in[2];
    const float* b1  = (const float*)d_in[3];
    const float* W2  = (const float*)d_in[4];
    const float* b2  = (const float*)d_in[5];
    float* out = (float*)d_out;

    float* rp;
    __half* g16p;
    uint4* Bpp;
    uint2 *App, *Ahpp, *Bp2p;
    cudaGetSymbolAddress((void**)&g16p, g_g16);
    cudaGetSymbolAddress((void**)&Bpp, g_Bp);
    cudaGetSymbolAddress((void**)&App, g_Ap);
    cudaGetSymbolAddress((void**)&Ahpp, g_Ahp);
    cudaGetSymbolAddress((void**)&Bp2p, g_Bp2);
    cudaGetSymbolAddress((void**)&rp, g_r);

    cudaFuncSetAttribute(fused_pre, cudaFuncAttributeMaxDynamicSharedMemorySize,
                         PRE_SMEM);
    cudaFuncSetAttribute(gemm2_fp16, cudaFuncAttributeMaxDynamicSharedMemorySize,
                         G2_SMEM);
    cudaFuncSetAttribute(gemm3_fp16, cudaFuncAttributeMaxDynamicSharedMemorySize,
                         G3_SMEM);

    // gemm1 || rowsum+pack || W2 pack
    fused_pre<<<656, 256, PRE_SMEM>>>(adj, rp, App, x, W1, Ahpp, b1, W2, Bp2p);
    // g = r ⊙ (h1 @ W2^T + b2)  (fp16 MMA) -> g16 + Bp
    gemm2_fp16<<<dim3(2, 64), 256, G2_SMEM>>>(Ahpp, Bp2p, b2, rp, g16p, (char*)Bpp);
    // out = diag(r) * (adj @ g + g)  (fp16 MMA, 2 ktiles per barrier)
    gemm3_fp16<<<dim3(2, 64), 256, G3_SMEM>>>(App, Bpp, g16p, rp, out);
}